// round 1
// baseline (speedup 1.0000x reference)
#include <cuda_runtime.h>
#include <cuda_bf16.h>

#define B_   2
#define S_   2048
#define D_   1024
#define H_   16
#define DK_  64
#define BS_  (B_*S_)            // 4096
#define NBH_ (B_*H_)            // 32

// scratch (device globals — no allocations allowed in kernel_launch)
__device__ float g_Q[NBH_ * S_ * DK_];     // [b,h,s,d]  16 MB
__device__ float g_K[NBH_ * S_ * DK_];
__device__ float g_V[NBH_ * S_ * DK_];
__device__ float g_ctx[BS_ * D_];          // [b,s,h*dk] 16 MB
__device__ float g_attn_fb[(size_t)NBH_ * S_ * S_]; // fallback if d_out lacks attn (512 MB)

// ---------------------------------------------------------------------------
// Kernel 1: QKV projection. P = x @ W^T + bias, stored head-split [b,h,s,d].
// M=4096, N=1024, K=1024. Tile 64x64, BK=16, block 16x16, 4x4 microtile.
// blockIdx.z selects Q/K/V.
// ---------------------------------------------------------------------------
__global__ __launch_bounds__(256)
void qkv_proj_kernel(const float* __restrict__ x,
                     const float* __restrict__ wq, const float* __restrict__ bq,
                     const float* __restrict__ wk, const float* __restrict__ bk,
                     const float* __restrict__ wv, const float* __restrict__ bv)
{
    const float* W; const float* bias; float* dst;
    if (blockIdx.z == 0)      { W = wq; bias = bq; dst = g_Q; }
    else if (blockIdx.z == 1) { W = wk; bias = bk; dst = g_K; }
    else                      { W = wv; bias = bv; dst = g_V; }

    __shared__ float As[16][64];
    __shared__ float Bs[16][64];

    const int m0 = blockIdx.y * 64;
    const int n0 = blockIdx.x * 64;
    const int tx = threadIdx.x, ty = threadIdx.y;
    const int tid = ty * 16 + tx;
    const int lr = tid >> 2;          // 0..63
    const int lc = (tid & 3) * 4;     // 0,4,8,12

    float acc[4][4] = {};

    for (int k0 = 0; k0 < D_; k0 += 16) {
        float4 av = *(const float4*)&x[(size_t)(m0 + lr) * D_ + k0 + lc];
        float4 bv4 = *(const float4*)&W[(size_t)(n0 + lr) * D_ + k0 + lc];
        As[lc+0][lr] = av.x;  As[lc+1][lr] = av.y;  As[lc+2][lr] = av.z;  As[lc+3][lr] = av.w;
        Bs[lc+0][lr] = bv4.x; Bs[lc+1][lr] = bv4.y; Bs[lc+2][lr] = bv4.z; Bs[lc+3][lr] = bv4.w;
        __syncthreads();
        #pragma unroll
        for (int kk = 0; kk < 16; kk++) {
            float4 a4 = *(const float4*)&As[kk][ty * 4];
            float4 b4 = *(const float4*)&Bs[kk][tx * 4];
            float a[4] = {a4.x, a4.y, a4.z, a4.w};
            float b[4] = {b4.x, b4.y, b4.z, b4.w};
            #pragma unroll
            for (int i = 0; i < 4; i++)
                #pragma unroll
                for (int j = 0; j < 4; j++)
                    acc[i][j] += a[i] * b[j];
        }
        __syncthreads();
    }

    #pragma unroll
    for (int i = 0; i < 4; i++) {
        const int m = m0 + ty * 4 + i;
        const int bb = m >> 11;          // m / 2048
        const int s  = m & 2047;
        #pragma unroll
        for (int j = 0; j < 4; j++) {
            const int n = n0 + tx * 4 + j;
            const int h = n >> 6;
            const int d = n & 63;
            dst[(((size_t)(bb * H_ + h)) * S_ + s) * DK_ + d] = acc[i][j] + bias[n];
        }
    }
}

// ---------------------------------------------------------------------------
// Kernel 2: scores = Q @ K^T / 8 per (b,h). M=N=2048, K=64.
// ---------------------------------------------------------------------------
__global__ __launch_bounds__(256)
void scores_kernel(float* __restrict__ attn_arg)
{
    float* attn = attn_arg ? attn_arg : g_attn_fb;
    const int bh = blockIdx.z;
    const float* Q  = g_Q + (size_t)bh * S_ * DK_;
    const float* Kp = g_K + (size_t)bh * S_ * DK_;
    float* C = attn + (size_t)bh * S_ * S_;

    __shared__ float As[16][64];
    __shared__ float Bs[16][64];

    const int m0 = blockIdx.y * 64;
    const int n0 = blockIdx.x * 64;
    const int tx = threadIdx.x, ty = threadIdx.y;
    const int tid = ty * 16 + tx;
    const int lr = tid >> 2;
    const int lc = (tid & 3) * 4;

    float acc[4][4] = {};

    for (int k0 = 0; k0 < DK_; k0 += 16) {
        float4 av  = *(const float4*)&Q [(size_t)(m0 + lr) * DK_ + k0 + lc];
        float4 bv4 = *(const float4*)&Kp[(size_t)(n0 + lr) * DK_ + k0 + lc];
        As[lc+0][lr] = av.x;  As[lc+1][lr] = av.y;  As[lc+2][lr] = av.z;  As[lc+3][lr] = av.w;
        Bs[lc+0][lr] = bv4.x; Bs[lc+1][lr] = bv4.y; Bs[lc+2][lr] = bv4.z; Bs[lc+3][lr] = bv4.w;
        __syncthreads();
        #pragma unroll
        for (int kk = 0; kk < 16; kk++) {
            float4 a4 = *(const float4*)&As[kk][ty * 4];
            float4 b4 = *(const float4*)&Bs[kk][tx * 4];
            float a[4] = {a4.x, a4.y, a4.z, a4.w};
            float b[4] = {b4.x, b4.y, b4.z, b4.w};
            #pragma unroll
            for (int i = 0; i < 4; i++)
                #pragma unroll
                for (int j = 0; j < 4; j++)
                    acc[i][j] += a[i] * b[j];
        }
        __syncthreads();
    }

    #pragma unroll
    for (int i = 0; i < 4; i++) {
        const int m = m0 + ty * 4 + i;
        #pragma unroll
        for (int j = 0; j < 4; j++) {
            const int n = n0 + tx * 4 + j;
            C[(size_t)m * S_ + n] = acc[i][j] * 0.125f;
        }
    }
}

// ---------------------------------------------------------------------------
// Kernel 3: row softmax over attn rows of length 2048, in place.
// One block (256 threads) per row; 65536 rows.
// ---------------------------------------------------------------------------
__global__ __launch_bounds__(256)
void softmax_kernel(float* __restrict__ attn_arg)
{
    float* attn = attn_arg ? attn_arg : g_attn_fb;
    float* p = attn + (size_t)blockIdx.x * S_;

    const int tid  = threadIdx.x;
    const int lane = tid & 31;
    const int warp = tid >> 5;
    __shared__ float red[8];

    float4* p4 = (float4*)p;
    float4 v0 = p4[tid];
    float4 v1 = p4[tid + 256];

    float mx = fmaxf(fmaxf(fmaxf(v0.x, v0.y), fmaxf(v0.z, v0.w)),
                     fmaxf(fmaxf(v1.x, v1.y), fmaxf(v1.z, v1.w)));
    #pragma unroll
    for (int o = 16; o; o >>= 1) mx = fmaxf(mx, __shfl_xor_sync(0xffffffffu, mx, o));
    if (lane == 0) red[warp] = mx;
    __syncthreads();
    mx = red[0];
    #pragma unroll
    for (int w = 1; w < 8; w++) mx = fmaxf(mx, red[w]);
    __syncthreads();

    v0.x = __expf(v0.x - mx); v0.y = __expf(v0.y - mx);
    v0.z = __expf(v0.z - mx); v0.w = __expf(v0.w - mx);
    v1.x = __expf(v1.x - mx); v1.y = __expf(v1.y - mx);
    v1.z = __expf(v1.z - mx); v1.w = __expf(v1.w - mx);

    float sm = (v0.x + v0.y) + (v0.z + v0.w) + (v1.x + v1.y) + (v1.z + v1.w);
    #pragma unroll
    for (int o = 16; o; o >>= 1) sm += __shfl_xor_sync(0xffffffffu, sm, o);
    if (lane == 0) red[warp] = sm;
    __syncthreads();
    sm = red[0];
    #pragma unroll
    for (int w = 1; w < 8; w++) sm += red[w];

    const float inv = 1.0f / sm;
    v0.x *= inv; v0.y *= inv; v0.z *= inv; v0.w *= inv;
    v1.x *= inv; v1.y *= inv; v1.z *= inv; v1.w *= inv;
    p4[tid] = v0;
    p4[tid + 256] = v1;
}

// ---------------------------------------------------------------------------
// Kernel 4: ctx = attn @ V per (b,h). NN GEMM, M=2048, N=64, K=2048.
// Output stored [b, s, h*64+d] (merge-heads layout).
// ---------------------------------------------------------------------------
__global__ __launch_bounds__(256)
void pv_kernel(const float* __restrict__ attn_arg)
{
    const float* attn = attn_arg ? attn_arg : g_attn_fb;
    const int bh = blockIdx.z;
    const float* A = attn + (size_t)bh * S_ * S_;
    const float* V = g_V + (size_t)bh * S_ * DK_;
    const int bb = bh >> 4;   // bh / 16
    const int h  = bh & 15;

    __shared__ float As[16][64];
    __shared__ float Bs[16][64];

    const int m0 = blockIdx.y * 64;
    const int tx = threadIdx.x, ty = threadIdx.y;
    const int tid = ty * 16 + tx;
    const int lr  = tid >> 2;
    const int lc  = (tid & 3) * 4;
    const int bkk = tid >> 4;         // 0..15
    const int bd4 = (tid & 15) * 4;   // 0..60

    float acc[4][4] = {};

    for (int k0 = 0; k0 < S_; k0 += 16) {
        float4 av = *(const float4*)&A[(size_t)(m0 + lr) * S_ + k0 + lc];
        float4 bv4 = *(const float4*)&V[(size_t)(k0 + bkk) * DK_ + bd4];
        As[lc+0][lr] = av.x; As[lc+1][lr] = av.y; As[lc+2][lr] = av.z; As[lc+3][lr] = av.w;
        Bs[bkk][bd4+0] = bv4.x; Bs[bkk][bd4+1] = bv4.y;
        Bs[bkk][bd4+2] = bv4.z; Bs[bkk][bd4+3] = bv4.w;
        __syncthreads();
        #pragma unroll
        for (int kk = 0; kk < 16; kk++) {
            float4 a4 = *(const float4*)&As[kk][ty * 4];
            float4 b4 = *(const float4*)&Bs[kk][tx * 4];
            float a[4] = {a4.x, a4.y, a4.z, a4.w};
            float b[4] = {b4.x, b4.y, b4.z, b4.w};
            #pragma unroll
            for (int i = 0; i < 4; i++)
                #pragma unroll
                for (int j = 0; j < 4; j++)
                    acc[i][j] += a[i] * b[j];
        }
        __syncthreads();
    }

    #pragma unroll
    for (int i = 0; i < 4; i++) {
        const int s = m0 + ty * 4 + i;
        #pragma unroll
        for (int j = 0; j < 4; j++) {
            const int d = tx * 4 + j;
            g_ctx[((size_t)(bb * S_ + s)) * D_ + h * DK_ + d] = acc[i][j];
        }
    }
}

// ---------------------------------------------------------------------------
// Kernel 5: out = ctx @ w_o^T + b_o. M=4096, N=1024, K=1024.
// ---------------------------------------------------------------------------
__global__ __launch_bounds__(256)
void oproj_kernel(const float* __restrict__ wo, const float* __restrict__ bo,
                  float* __restrict__ out)
{
    __shared__ float As[16][64];
    __shared__ float Bs[16][64];

    const int m0 = blockIdx.y * 64;
    const int n0 = blockIdx.x * 64;
    const int tx = threadIdx.x, ty = threadIdx.y;
    const int tid = ty * 16 + tx;
    const int lr = tid >> 2;
    const int lc = (tid & 3) * 4;

    float acc[4][4] = {};

    for (int k0 = 0; k0 < D_; k0 += 16) {
        float4 av  = *(const float4*)&g_ctx[(size_t)(m0 + lr) * D_ + k0 + lc];
        float4 bv4 = *(const float4*)&wo  [(size_t)(n0 + lr) * D_ + k0 + lc];
        As[lc+0][lr] = av.x;  As[lc+1][lr] = av.y;  As[lc+2][lr] = av.z;  As[lc+3][lr] = av.w;
        Bs[lc+0][lr] = bv4.x; Bs[lc+1][lr] = bv4.y; Bs[lc+2][lr] = bv4.z; Bs[lc+3][lr] = bv4.w;
        __syncthreads();
        #pragma unroll
        for (int kk = 0; kk < 16; kk++) {
            float4 a4 = *(const float4*)&As[kk][ty * 4];
            float4 b4 = *(const float4*)&Bs[kk][tx * 4];
            float a[4] = {a4.x, a4.y, a4.z, a4.w};
            float b[4] = {b4.x, b4.y, b4.z, b4.w};
            #pragma unroll
            for (int i = 0; i < 4; i++)
                #pragma unroll
                for (int j = 0; j < 4; j++)
                    acc[i][j] += a[i] * b[j];
        }
        __syncthreads();
    }

    #pragma unroll
    for (int i = 0; i < 4; i++) {
        const int m = m0 + ty * 4 + i;
        #pragma unroll
        for (int j = 0; j < 4; j++) {
            const int n = n0 + tx * 4 + j;
            out[(size_t)m * D_ + n] = acc[i][j] + bo[n];
        }
    }
}

// ---------------------------------------------------------------------------
extern "C" void kernel_launch(void* const* d_in, const int* in_sizes, int n_in,
                              void* d_out, int out_size)
{
    const float* x  = (const float*)d_in[0];
    const float* wq = (const float*)d_in[1];
    const float* bq = (const float*)d_in[2];
    const float* wk = (const float*)d_in[3];
    const float* bk = (const float*)d_in[4];
    const float* wv = (const float*)d_in[5];
    const float* bv = (const float*)d_in[6];
    const float* wo = (const float*)d_in[7];
    const float* bo = (const float*)d_in[8];

    float* out = (float*)d_out;
    const long long OUT_E  = (long long)BS_ * D_;                 // 4,194,304
    const long long ATTN_E = (long long)NBH_ * S_ * S_;           // 134,217,728
    // attn goes into d_out tail if the harness expects it; else device scratch
    float* attn = ((long long)out_size >= OUT_E + ATTN_E) ? (out + OUT_E) : nullptr;

    dim3 blk(16, 16);

    // 1. QKV projections
    qkv_proj_kernel<<<dim3(D_/64, BS_/64, 3), blk>>>(x, wq, bq, wk, bk, wv, bv);

    // 2. scores = Q K^T / 8
    scores_kernel<<<dim3(S_/64, S_/64, NBH_), blk>>>(attn);

    // 3. softmax rows
    softmax_kernel<<<NBH_ * S_, 256>>>(attn);

    // 4. ctx = attn @ V
    pv_kernel<<<dim3(1, S_/64, NBH_), blk>>>(attn);

    // 5. out = ctx @ w_o^T + b_o
    oproj_kernel<<<dim3(D_/64, BS_/64), blk>>>(wo, bo, out);
}

// round 2
// speedup vs baseline: 2.6185x; 2.6185x over previous
#include <cuda_runtime.h>
#include <cuda_bf16.h>

#define B_   2
#define S_   2048
#define D_   1024
#define H_   16
#define DK_  64
#define BS_  (B_*S_)            // 4096
#define NBH_ (B_*H_)            // 32

// ---------------- device scratch (no allocations allowed) -------------------
__device__ __nv_bfloat16 g_xh[BS_ * D_],  g_xl[BS_ * D_];       // x split
__device__ __nv_bfloat16 g_w3h[3 * D_ * D_], g_w3l[3 * D_ * D_]; // wq|wk|wv
__device__ __nv_bfloat16 g_woh[D_ * D_], g_wol[D_ * D_];
__device__ __nv_bfloat16 g_qh[NBH_ * S_ * DK_], g_ql[NBH_ * S_ * DK_];
__device__ __nv_bfloat16 g_kh[NBH_ * S_ * DK_], g_kl[NBH_ * S_ * DK_];
__device__ __nv_bfloat16 g_vth[NBH_ * DK_ * S_], g_vtl[NBH_ * DK_ * S_]; // V^T [bh][d][s]
__device__ __nv_bfloat16 g_ch[BS_ * D_], g_cl[BS_ * D_];        // ctx split
__device__ float g_attn_fb[(size_t)NBH_ * S_ * S_];             // fallback

// ---------------- smem layout (per stage) ------------------------------
// A tile 128x64 bf16 (hi,lo) = 16KB each ; B tile 64x64 bf16 (hi,lo) = 8KB each
#define OFF_AH 0
#define OFF_AL 16384
#define OFF_BH 32768
#define OFF_BL 40960
#define STAGE_BYTES 49152

// ---------------- helpers ---------------------------------------------------
__device__ __forceinline__ unsigned smem_u32(const void* p) {
    return (unsigned)__cvta_generic_to_shared(p);
}

__device__ __forceinline__ void ldsm4(unsigned r[4], unsigned addr) {
    asm volatile("ldmatrix.sync.aligned.m8n8.x4.shared.b16 {%0,%1,%2,%3}, [%4];\n"
                 : "=r"(r[0]), "=r"(r[1]), "=r"(r[2]), "=r"(r[3]) : "r"(addr));
}

__device__ __forceinline__ void mma16816(float (&d)[4], const unsigned a[4],
                                         unsigned b0, unsigned b1) {
    asm volatile(
        "mma.sync.aligned.m16n8k16.row.col.f32.bf16.bf16.f32 "
        "{%0,%1,%2,%3}, {%4,%5,%6,%7}, {%8,%9}, {%0,%1,%2,%3};\n"
        : "+f"(d[0]), "+f"(d[1]), "+f"(d[2]), "+f"(d[3])
        : "r"(a[0]), "r"(a[1]), "r"(a[2]), "r"(a[3]), "r"(b0), "r"(b1));
}

// split two floats into packed hi/lo bf16x2
__device__ __forceinline__ void split2(float x, float y, unsigned &h, unsigned &l) {
    __nv_bfloat162 hv = __floats2bfloat162_rn(x, y);
    float rx = x - __low2float(hv);
    float ry = y - __high2float(hv);
    __nv_bfloat162 lv = __floats2bfloat162_rn(rx, ry);
    h = *reinterpret_cast<unsigned*>(&hv);
    l = *reinterpret_cast<unsigned*>(&lv);
}

// swizzled smem byte offset: row stride 128B, 16B chunks XOR'd by row&7
__device__ __forceinline__ unsigned swz(int row, int kb) {
    return (unsigned)(row * 128 + (kb ^ ((row & 7) << 4)));
}

// ---------------- staging ----------------------------------------------------
__device__ __forceinline__ void loadA_bf16(uint4 rh[4], uint4 rl[4],
    const __nv_bfloat16* __restrict__ Ah, const __nv_bfloat16* __restrict__ Al,
    int ld, int m0, int k0, int tid)
{
#pragma unroll
    for (int j = 0; j < 4; j++) {
        int id = tid + j * 256, row = id >> 3, c = id & 7;
        size_t g = (size_t)(m0 + row) * ld + k0 + c * 8;
        rh[j] = *reinterpret_cast<const uint4*>(Ah + g);
        rl[j] = *reinterpret_cast<const uint4*>(Al + g);
    }
}
__device__ __forceinline__ void storeA(char* base, const uint4 rh[4], const uint4 rl[4], int tid)
{
#pragma unroll
    for (int j = 0; j < 4; j++) {
        int id = tid + j * 256, row = id >> 3, c = id & 7;
        unsigned off = swz(row, c * 16);
        *reinterpret_cast<uint4*>(base + OFF_AH + off) = rh[j];
        *reinterpret_cast<uint4*>(base + OFF_AL + off) = rl[j];
    }
}
__device__ __forceinline__ void loadB_bf16(uint4 rh[2], uint4 rl[2],
    const __nv_bfloat16* __restrict__ Bh, const __nv_bfloat16* __restrict__ Bl,
    int ld, int n0, int k0, int tid)
{
#pragma unroll
    for (int j = 0; j < 2; j++) {
        int id = tid + j * 256, row = id >> 3, c = id & 7;
        size_t g = (size_t)(n0 + row) * ld + k0 + c * 8;
        rh[j] = *reinterpret_cast<const uint4*>(Bh + g);
        rl[j] = *reinterpret_cast<const uint4*>(Bl + g);
    }
}
__device__ __forceinline__ void storeB(char* base, const uint4 rh[2], const uint4 rl[2], int tid)
{
#pragma unroll
    for (int j = 0; j < 2; j++) {
        int id = tid + j * 256, row = id >> 3, c = id & 7;
        unsigned off = swz(row, c * 16);
        *reinterpret_cast<uint4*>(base + OFF_BH + off) = rh[j];
        *reinterpret_cast<uint4*>(base + OFF_BL + off) = rl[j];
    }
}
// fp32 A staging (attn) — load
__device__ __forceinline__ void loadA_f32(float4 rf[8],
    const float* __restrict__ A, int ld, int m0, int k0, int tid)
{
#pragma unroll
    for (int j = 0; j < 4; j++) {
        int id = tid + j * 256, row = id >> 3, c = id & 7;
        size_t g = (size_t)(m0 + row) * ld + k0 + c * 8;
        rf[2 * j]     = *reinterpret_cast<const float4*>(A + g);
        rf[2 * j + 1] = *reinterpret_cast<const float4*>(A + g + 4);
    }
}
// fp32 A staging — split+store
__device__ __forceinline__ void storeA_f32(char* base, const float4 rf[8], int tid)
{
#pragma unroll
    for (int j = 0; j < 4; j++) {
        int id = tid + j * 256, row = id >> 3, c = id & 7;
        const float4 f0 = rf[2 * j], f1 = rf[2 * j + 1];
        uint4 hi, lo;
        split2(f0.x, f0.y, hi.x, lo.x);
        split2(f0.z, f0.w, hi.y, lo.y);
        split2(f1.x, f1.y, hi.z, lo.z);
        split2(f1.z, f1.w, hi.w, lo.w);
        unsigned off = swz(row, c * 16);
        *reinterpret_cast<uint4*>(base + OFF_AH + off) = hi;
        *reinterpret_cast<uint4*>(base + OFF_AL + off) = lo;
    }
}

// ---------------- core compute over one BK=64 stage -------------------------
__device__ __forceinline__ void compute_stage(const char* base, int wm, int wn,
                                              int lane, float acc[2][4][4])
{
    unsigned sb = smem_u32(base);
    const int arow0 = wm * 32 + (lane & 15);
    const int akh   = ((lane >> 4) & 1) * 16;
    const int brow0 = wn * 32 + ((lane >> 4) & 1) * 8 + (lane & 7);
    const int bkh   = ((lane >> 3) & 1) * 16;
#pragma unroll
    for (int ks = 0; ks < 4; ks++) {
        unsigned ah[2][4], al[2][4], bh[2][4], bl[2][4];
#pragma unroll
        for (int mt = 0; mt < 2; mt++) {
            unsigned off = swz(arow0 + mt * 16, ks * 32 + akh);
            ldsm4(ah[mt], sb + OFF_AH + off);
            ldsm4(al[mt], sb + OFF_AL + off);
        }
#pragma unroll
        for (int p = 0; p < 2; p++) {
            unsigned off = swz(brow0 + p * 16, ks * 32 + bkh);
            ldsm4(bh[p], sb + OFF_BH + off);
            ldsm4(bl[p], sb + OFF_BL + off);
        }
#pragma unroll
        for (int mt = 0; mt < 2; mt++)
#pragma unroll
            for (int nt = 0; nt < 4; nt++) {
                unsigned b0h = bh[nt >> 1][(nt & 1) * 2], b1h = bh[nt >> 1][(nt & 1) * 2 + 1];
                unsigned b0l = bl[nt >> 1][(nt & 1) * 2], b1l = bl[nt >> 1][(nt & 1) * 2 + 1];
                mma16816(acc[mt][nt], ah[mt], b0h, b1h);
                mma16816(acc[mt][nt], ah[mt], b0l, b1l);
                mma16816(acc[mt][nt], al[mt], b0h, b1h);
            }
    }
}

// ---------------- kernel: split fp32 -> hi/lo bf16 --------------------------
__global__ void split_kernel(const float* __restrict__ src, int which, int n)
{
    __nv_bfloat16 *hi, *lo;
    switch (which) {
        case 0:  hi = g_xh;            lo = g_xl;            break;
        case 1:  hi = g_w3h;           lo = g_w3l;           break;
        case 2:  hi = g_w3h + D_*D_;   lo = g_w3l + D_*D_;   break;
        case 3:  hi = g_w3h + 2*D_*D_; lo = g_w3l + 2*D_*D_; break;
        default: hi = g_woh;           lo = g_wol;           break;
    }
    int i = (blockIdx.x * blockDim.x + threadIdx.x) * 2;
    if (i < n) {
        unsigned h, l;
        split2(src[i], src[i + 1], h, l);
        *reinterpret_cast<unsigned*>(hi + i) = h;
        *reinterpret_cast<unsigned*>(lo + i) = l;
    }
}

// ---------------- kernel 1: fused QKV projection ----------------------------
// C[M=4096, N=3072] = x @ W3^T + bias ; epilogue -> Q/K head-split hi/lo, V^T hi/lo
__global__ __launch_bounds__(256) void qkv_gemm(const float* __restrict__ bq,
                                                const float* __restrict__ bk,
                                                const float* __restrict__ bv)
{
    extern __shared__ char sm[];
    const int m0 = blockIdx.y * 128, n0 = blockIdx.x * 64;
    const int tid = threadIdx.x, lane = tid & 31, wid = tid >> 5;
    const int wm = wid >> 1, wn = wid & 1;

    float acc[2][4][4] = {};
    uint4 rah[4], ral[4], rbh[2], rbl[2];

    loadA_bf16(rah, ral, g_xh, g_xl, D_, m0, 0, tid);
    loadB_bf16(rbh, rbl, g_w3h, g_w3l, D_, n0, 0, tid);
    storeA(sm, rah, ral, tid);
    storeB(sm, rbh, rbl, tid);
    __syncthreads();

    for (int it = 0; it < 16; it++) {
        const int cur = it & 1;
        if (it + 1 < 16) {
            loadA_bf16(rah, ral, g_xh, g_xl, D_, m0, (it + 1) * 64, tid);
            loadB_bf16(rbh, rbl, g_w3h, g_w3l, D_, n0, (it + 1) * 64, tid);
        }
        compute_stage(sm + cur * STAGE_BYTES, wm, wn, lane, acc);
        if (it + 1 < 16) {
            storeA(sm + (1 - cur) * STAGE_BYTES, rah, ral, tid);
            storeB(sm + (1 - cur) * STAGE_BYTES, rbh, rbl, tid);
        }
        __syncthreads();
    }

    // epilogue — region/head constant per block (n0 multiple of 64)
    const int reg = n0 >> 10;                 // 0=Q,1=K,2=V
    const int h   = (n0 & 1023) >> 6;
    const float* bp = (reg == 0) ? bq : (reg == 1) ? bk : bv;
    __nv_bfloat16* dH = (reg == 0) ? g_qh : g_kh;
    __nv_bfloat16* dL = (reg == 0) ? g_ql : g_kl;
    const int tm0 = m0 + wm * 32, tn0 = n0 + wn * 32;

#pragma unroll
    for (int mt = 0; mt < 2; mt++)
#pragma unroll
        for (int nt = 0; nt < 4; nt++) {
            const int c  = tn0 + nt * 8 + 2 * (lane & 3);
            const int d  = c & 63;
            const float bias0 = bp[c & 1023], bias1 = bp[(c & 1023) + 1];
#pragma unroll
            for (int half = 0; half < 2; half++) {
                const int m = tm0 + mt * 16 + (lane >> 2) + half * 8;
                const float v0 = acc[mt][nt][half * 2]     + bias0;
                const float v1 = acc[mt][nt][half * 2 + 1] + bias1;
                const int b = m >> 11, s = m & 2047;
                const size_t bh = (size_t)(b * H_ + h);
                unsigned hh, ll;
                split2(v0, v1, hh, ll);
                if (reg < 2) {
                    size_t idx = (bh * S_ + s) * DK_ + d;
                    *reinterpret_cast<unsigned*>(dH + idx) = hh;
                    *reinterpret_cast<unsigned*>(dL + idx) = ll;
                } else {
                    size_t i0 = (bh * DK_ + d) * S_ + s;
                    __nv_bfloat162 hv = *reinterpret_cast<__nv_bfloat162*>(&hh);
                    __nv_bfloat162 lv = *reinterpret_cast<__nv_bfloat162*>(&ll);
                    g_vth[i0]      = __low2bfloat16(hv);
                    g_vtl[i0]      = __low2bfloat16(lv);
                    g_vth[i0 + S_] = __high2bfloat16(hv);
                    g_vtl[i0 + S_] = __high2bfloat16(lv);
                }
            }
        }
}

// ---------------- kernel 2: scores = Q K^T / 8 -------------------------------
__global__ __launch_bounds__(256) void scores_gemm(float* __restrict__ attn_arg)
{
    extern __shared__ char sm[];
    float* attn = attn_arg ? attn_arg : g_attn_fb;
    const int bh = blockIdx.z;
    const int m0 = blockIdx.y * 128, n0 = blockIdx.x * 64;
    const int tid = threadIdx.x, lane = tid & 31, wid = tid >> 5;
    const int wm = wid >> 1, wn = wid & 1;

    const __nv_bfloat16* Ah = g_qh + (size_t)bh * S_ * DK_;
    const __nv_bfloat16* Al = g_ql + (size_t)bh * S_ * DK_;
    const __nv_bfloat16* Bh = g_kh + (size_t)bh * S_ * DK_;
    const __nv_bfloat16* Bl = g_kl + (size_t)bh * S_ * DK_;

    float acc[2][4][4] = {};
    uint4 rah[4], ral[4], rbh[2], rbl[2];
    loadA_bf16(rah, ral, Ah, Al, DK_, m0, 0, tid);
    loadB_bf16(rbh, rbl, Bh, Bl, DK_, n0, 0, tid);
    storeA(sm, rah, ral, tid);
    storeB(sm, rbh, rbl, tid);
    __syncthreads();
    compute_stage(sm, wm, wn, lane, acc);

    float* C = attn + (size_t)bh * S_ * S_;
    const int tm0 = m0 + wm * 32, tn0 = n0 + wn * 32;
#pragma unroll
    for (int mt = 0; mt < 2; mt++)
#pragma unroll
        for (int nt = 0; nt < 4; nt++) {
            const int c = tn0 + nt * 8 + 2 * (lane & 3);
#pragma unroll
            for (int half = 0; half < 2; half++) {
                const int m = tm0 + mt * 16 + (lane >> 2) + half * 8;
                float2 v = { acc[mt][nt][half * 2] * 0.125f,
                             acc[mt][nt][half * 2 + 1] * 0.125f };
                *reinterpret_cast<float2*>(C + (size_t)m * S_ + c) = v;
            }
        }
}

// ---------------- kernel 3: softmax (fp32, in place) ------------------------
__global__ __launch_bounds__(256) void softmax_kernel(float* __restrict__ attn_arg)
{
    float* attn = attn_arg ? attn_arg : g_attn_fb;
    float* p = attn + (size_t)blockIdx.x * S_;
    const int tid = threadIdx.x, lane = tid & 31, warp = tid >> 5;
    __shared__ float red[8];

    float4* p4 = (float4*)p;
    float4 v0 = p4[tid];
    float4 v1 = p4[tid + 256];

    float mx = fmaxf(fmaxf(fmaxf(v0.x, v0.y), fmaxf(v0.z, v0.w)),
                     fmaxf(fmaxf(v1.x, v1.y), fmaxf(v1.z, v1.w)));
#pragma unroll
    for (int o = 16; o; o >>= 1) mx = fmaxf(mx, __shfl_xor_sync(0xffffffffu, mx, o));
    if (lane == 0) red[warp] = mx;
    __syncthreads();
    mx = red[0];
#pragma unroll
    for (int w = 1; w < 8; w++) mx = fmaxf(mx, red[w]);
    __syncthreads();

    v0.x = __expf(v0.x - mx); v0.y = __expf(v0.y - mx);
    v0.z = __expf(v0.z - mx); v0.w = __expf(v0.w - mx);
    v1.x = __expf(v1.x - mx); v1.y = __expf(v1.y - mx);
    v1.z = __expf(v1.z - mx); v1.w = __expf(v1.w - mx);

    float smv = (v0.x + v0.y) + (v0.z + v0.w) + (v1.x + v1.y) + (v1.z + v1.w);
#pragma unroll
    for (int o = 16; o; o >>= 1) smv += __shfl_xor_sync(0xffffffffu, smv, o);
    if (lane == 0) red[warp] = smv;
    __syncthreads();
    smv = red[0];
#pragma unroll
    for (int w = 1; w < 8; w++) smv += red[w];

    const float inv = 1.0f / smv;
    v0.x *= inv; v0.y *= inv; v0.z *= inv; v0.w *= inv;
    v1.x *= inv; v1.y *= inv; v1.z *= inv; v1.w *= inv;
    p4[tid] = v0;
    p4[tid + 256] = v1;
}

// ---------------- kernel 4: ctx = attn @ V ----------------------------------
__global__ __launch_bounds__(256) void pv_gemm(const float* __restrict__ attn_arg)
{
    extern __shared__ char sm[];
    const float* attn = attn_arg ? attn_arg : g_attn_fb;
    const int bh = blockIdx.z;
    const int m0 = blockIdx.y * 128;
    const int tid = threadIdx.x, lane = tid & 31, wid = tid >> 5;
    const int wm = wid >> 1, wn = wid & 1;

    const float* A = attn + (size_t)bh * S_ * S_;
    const __nv_bfloat16* Bh = g_vth + (size_t)bh * DK_ * S_;
    const __nv_bfloat16* Bl = g_vtl + (size_t)bh * DK_ * S_;

    float acc[2][4][4] = {};
    float4 rf[8];
    uint4 rbh[2], rbl[2];

    loadA_f32(rf, A, S_, m0, 0, tid);
    loadB_bf16(rbh, rbl, Bh, Bl, S_, 0, 0, tid);
    storeA_f32(sm, rf, tid);
    storeB(sm, rbh, rbl, tid);
    __syncthreads();

    for (int it = 0; it < 32; it++) {
        const int cur = it & 1;
        if (it + 1 < 32) {
            loadA_f32(rf, A, S_, m0, (it + 1) * 64, tid);
            loadB_bf16(rbh, rbl, Bh, Bl, S_, 0, (it + 1) * 64, tid);
        }
        compute_stage(sm + cur * STAGE_BYTES, wm, wn, lane, acc);
        if (it + 1 < 32) {
            storeA_f32(sm + (1 - cur) * STAGE_BYTES, rf, tid);
            storeB(sm + (1 - cur) * STAGE_BYTES, rbh, rbl, tid);
        }
        __syncthreads();
    }

    // epilogue -> ctx hi/lo [b, s, h*64 + d]
    const int b = bh >> 4, h = bh & 15;
    const int tm0 = m0 + wm * 32, tn0 = wn * 32;
#pragma unroll
    for (int mt = 0; mt < 2; mt++)
#pragma unroll
        for (int nt = 0; nt < 4; nt++) {
            const int c = tn0 + nt * 8 + 2 * (lane & 3);
#pragma unroll
            for (int half = 0; half < 2; half++) {
                const int s = tm0 + mt * 16 + (lane >> 2) + half * 8;
                unsigned hh, ll;
                split2(acc[mt][nt][half * 2], acc[mt][nt][half * 2 + 1], hh, ll);
                size_t idx = ((size_t)(b * S_ + s)) * D_ + h * DK_ + c;
                *reinterpret_cast<unsigned*>(g_ch + idx) = hh;
                *reinterpret_cast<unsigned*>(g_cl + idx) = ll;
            }
        }
}

// ---------------- kernel 5: out = ctx @ Wo^T + bo ----------------------------
__global__ __launch_bounds__(256) void oproj_gemm(const float* __restrict__ bo,
                                                  float* __restrict__ out)
{
    extern __shared__ char sm[];
    const int m0 = blockIdx.y * 128, n0 = blockIdx.x * 64;
    const int tid = threadIdx.x, lane = tid & 31, wid = tid >> 5;
    const int wm = wid >> 1, wn = wid & 1;

    float acc[2][4][4] = {};
    uint4 rah[4], ral[4], rbh[2], rbl[2];

    loadA_bf16(rah, ral, g_ch, g_cl, D_, m0, 0, tid);
    loadB_bf16(rbh, rbl, g_woh, g_wol, D_, n0, 0, tid);
    storeA(sm, rah, ral, tid);
    storeB(sm, rbh, rbl, tid);
    __syncthreads();

    for (int it = 0; it < 16; it++) {
        const int cur = it & 1;
        if (it + 1 < 16) {
            loadA_bf16(rah, ral, g_ch, g_cl, D_, m0, (it + 1) * 64, tid);
            loadB_bf16(rbh, rbl, g_woh, g_wol, D_, n0, (it + 1) * 64, tid);
        }
        compute_stage(sm + cur * STAGE_BYTES, wm, wn, lane, acc);
        if (it + 1 < 16) {
            storeA(sm + (1 - cur) * STAGE_BYTES, rah, ral, tid);
            storeB(sm + (1 - cur) * STAGE_BYTES, rbh, rbl, tid);
        }
        __syncthreads();
    }

    const int tm0 = m0 + wm * 32, tn0 = n0 + wn * 32;
#pragma unroll
    for (int mt = 0; mt < 2; mt++)
#pragma unroll
        for (int nt = 0; nt < 4; nt++) {
            const int c = tn0 + nt * 8 + 2 * (lane & 3);
            const float b0 = bo[c], b1 = bo[c + 1];
#pragma unroll
            for (int half = 0; half < 2; half++) {
                const int m = tm0 + mt * 16 + (lane >> 2) + half * 8;
                float2 v = { acc[mt][nt][half * 2] + b0,
                             acc[mt][nt][half * 2 + 1] + b1 };
                *reinterpret_cast<float2*>(out + (size_t)m * D_ + c) = v;
            }
        }
}

// ---------------------------------------------------------------------------
extern "C" void kernel_launch(void* const* d_in, const int* in_sizes, int n_in,
                              void* d_out, int out_size)
{
    const float* x  = (const float*)d_in[0];
    const float* wq = (const float*)d_in[1];
    const float* bq = (const float*)d_in[2];
    const float* wk = (const float*)d_in[3];
    const float* bk = (const float*)d_in[4];
    const float* wv = (const float*)d_in[5];
    const float* bv = (const float*)d_in[6];
    const float* wo = (const float*)d_in[7];
    const float* bo = (const float*)d_in[8];

    float* out = (float*)d_out;
    const long long OUT_E  = (long long)BS_ * D_;
    const long long ATTN_E = (long long)NBH_ * S_ * S_;
    float* attn = ((long long)out_size >= OUT_E + ATTN_E) ? (out + OUT_E) : nullptr;

    static bool attr_done = false;
    if (!attr_done) {
        cudaFuncSetAttribute(qkv_gemm,   cudaFuncAttributeMaxDynamicSharedMemorySize, 2 * STAGE_BYTES);
        cudaFuncSetAttribute(pv_gemm,    cudaFuncAttributeMaxDynamicSharedMemorySize, 2 * STAGE_BYTES);
        cudaFuncSetAttribute(oproj_gemm, cudaFuncAttributeMaxDynamicSharedMemorySize, 2 * STAGE_BYTES);
        cudaFuncSetAttribute(scores_gemm, cudaFuncAttributeMaxDynamicSharedMemorySize, STAGE_BYTES);
        attr_done = true;
    }

    // 0. precision splits
    split_kernel<<<(BS_ * D_ / 2 + 255) / 256, 256>>>(x,  0, BS_ * D_);
    split_kernel<<<(D_ * D_ / 2 + 255) / 256, 256>>>(wq, 1, D_ * D_);
    split_kernel<<<(D_ * D_ / 2 + 255) / 256, 256>>>(wk, 2, D_ * D_);
    split_kernel<<<(D_ * D_ / 2 + 255) / 256, 256>>>(wv, 3, D_ * D_);
    split_kernel<<<(D_ * D_ / 2 + 255) / 256, 256>>>(wo, 4, D_ * D_);

    // 1. QKV projection (fused N=3072)
    qkv_gemm<<<dim3(3 * D_ / 64, BS_ / 128), 256, 2 * STAGE_BYTES>>>(bq, bk, bv);

    // 2. scores
    scores_gemm<<<dim3(S_ / 64, S_ / 128, NBH_), 256, STAGE_BYTES>>>(attn);

    // 3. softmax
    softmax_kernel<<<NBH_ * S_, 256>>>(attn);

    // 4. ctx = attn @ V
    pv_gemm<<<dim3(1, S_ / 128, NBH_), 256, 2 * STAGE_BYTES>>>(attn);

    // 5. out projection
    oproj_gemm<<<dim3(D_ / 64, BS_ / 128), 256, 2 * STAGE_BYTES>>>(bo, out);
}